// round 13
// baseline (speedup 1.0000x reference)
#include <cuda_runtime.h>
#include <math.h>

#define BATCH 4096
#define D1 10816
#define D2 128
#define NEXP 8
#define KSPLIT 5408

#define G1_OFF (BATCH*10)
#define G2_OFF (G1_OFF + BATCH*8)
#define LOSS_OFF (G2_OFF + BATCH*8)

typedef unsigned long long ull;

__device__ __forceinline__ ull f32x2_fma(ull a, ull b, ull c) {
    ull d; asm("fma.rn.f32x2 %0, %1, %2, %3;" : "=l"(d) : "l"(a), "l"(b), "l"(c)); return d;
}
__device__ __forceinline__ ull f32x2_dup(float x) {
    ull d; asm("mov.b64 %0, {%1, %1};" : "=l"(d) : "f"(x)); return d;
}
__device__ __forceinline__ ull f32x2_pack(float lo, float hi) {
    ull d; asm("mov.b64 %0, {%1, %2};" : "=l"(d) : "f"(lo), "f"(hi)); return d;
}
__device__ __forceinline__ float2 f32x2_unpack(ull v) {
    float2 r; asm("mov.b64 {%0, %1}, %2;" : "=f"(r.x), "=f"(r.y) : "l"(v)); return r;
}

// ---------------- scratch ----------------
__device__ float g_h1[(size_t)BATCH*32*28*28];
__device__ float g_h2[(size_t)BATCH*D1];
__device__ float g_lpart[(size_t)4*BATCH*8];
__device__ float g_wt[64*288];
__device__ int   g_cnt[NEXP];
__device__ int   g_tok[NEXP*BATCH];
__device__ float g_gate[NEXP*BATCH];
__device__ int   g_slot[NEXP*BATCH];
__device__ float g_ypart[(size_t)4*BATCH*D2];   // [2*dispatch_slot + khalf]

// ---------------- init + conv2 weight transpose ----------------
__global__ void init_transpose_kernel(const float* __restrict__ w) {
    int idx = blockIdx.x*256 + threadIdx.x;
    if (idx < NEXP) g_cnt[idx] = 0;
    if (idx < 64*288) {
        int ocl = idx & 15;
        int r = idx >> 4;
        int tap = r % 9;
        int r2 = r / 9;
        int ic = r2 & 31;
        int ocg = r2 >> 5;
        g_wt[idx] = w[(ocg*16 + ocl)*288 + ic*9 + tap];
    }
}

// profiler-alignment no-op (keeps conv2pool in the profiled slot)
__global__ void dummy_kernel() {}

// ---------------- conv1 + relu (f32x2, oc-paired) ----------------
__global__ void conv1_kernel(const float* __restrict__ x,
                             const float* __restrict__ w,
                             const float* __restrict__ b) {
    __shared__ float sw2[288];
    __shared__ float sb[32];
    int n = blockIdx.x, tid = threadIdx.x;
    for (int i = tid; i < 288; i += blockDim.x) {
        int oc = i / 9, t = i % 9;
        sw2[t*32 + oc] = w[i];
    }
    if (tid < 32) sb[tid] = b[tid];
    __syncthreads();
    const float* xr = x + (size_t)n * 900;
    for (int pos = tid; pos < 784; pos += blockDim.x) {
        int i = pos / 28, j = pos % 28;
        ull pd[9];
#pragma unroll
        for (int a = 0; a < 3; a++)
#pragma unroll
            for (int c = 0; c < 3; c++)
                pd[a*3+c] = f32x2_dup(xr[(i+a)*30 + j + c]);
        ull acc[16];
#pragma unroll
        for (int o = 0; o < 16; o++) acc[o] = f32x2_pack(sb[2*o], sb[2*o+1]);
#pragma unroll
        for (int t = 0; t < 9; t++) {
            const ull* wr = (const ull*)&sw2[t*32];
#pragma unroll
            for (int o = 0; o < 16; o++)
                acc[o] = f32x2_fma(wr[o], pd[t], acc[o]);
        }
#pragma unroll
        for (int o = 0; o < 16; o++) {
            float2 v = f32x2_unpack(acc[o]);
            g_h1[((size_t)n*32 + 2*o)*784 + pos]   = fmaxf(v.x, 0.f);
            g_h1[((size_t)n*32 + 2*o+1)*784 + pos] = fmaxf(v.y, 0.f);
        }
    }
}

// dup 4 consecutive input pixels into f32x2 regs
#define LOAD_DUP(dst, p) { \
    float2 _u0 = *(const float2*)(p); \
    float2 _u1 = *(const float2*)((p)+2); \
    dst[0] = f32x2_dup(_u0.x); dst[1] = f32x2_dup(_u0.y); \
    dst[2] = f32x2_dup(_u1.x); dst[3] = f32x2_dup(_u1.y); }

#define ROW_TAPS(a, rlo, rhi) { \
_Pragma("unroll") \
    for (int c = 0; c < 3; c++) { \
        const ulonglong2* _w = (const ulonglong2*)&sw[((3*(a)+c)*16) + woff]; \
        ulonglong2 wA = _w[0], wB = _w[1], wC = _w[2], wD = _w[3]; \
_Pragma("unroll") \
        for (int s = 0; s < 2; s++) { \
            ull p0 = rlo[c+s], p1 = rhi[c+s]; \
            acc[0][s]   = f32x2_fma(wA.x, p0, acc[0][s]); \
            acc[1][s]   = f32x2_fma(wA.y, p0, acc[1][s]); \
            acc[2][s]   = f32x2_fma(wB.x, p0, acc[2][s]); \
            acc[3][s]   = f32x2_fma(wB.y, p0, acc[3][s]); \
            acc[4][s]   = f32x2_fma(wC.x, p0, acc[4][s]); \
            acc[5][s]   = f32x2_fma(wC.y, p0, acc[5][s]); \
            acc[6][s]   = f32x2_fma(wD.x, p0, acc[6][s]); \
            acc[7][s]   = f32x2_fma(wD.y, p0, acc[7][s]); \
            acc[0][2+s] = f32x2_fma(wA.x, p1, acc[0][2+s]); \
            acc[1][2+s] = f32x2_fma(wA.y, p1, acc[1][2+s]); \
            acc[2][2+s] = f32x2_fma(wB.x, p1, acc[2][2+s]); \
            acc[3][2+s] = f32x2_fma(wB.y, p1, acc[3][2+s]); \
            acc[4][2+s] = f32x2_fma(wC.x, p1, acc[4][2+s]); \
            acc[5][2+s] = f32x2_fma(wC.y, p1, acc[5][2+s]); \
            acc[6][2+s] = f32x2_fma(wD.x, p1, acc[6][2+s]); \
            acc[7][2+s] = f32x2_fma(wD.y, p1, acc[7][2+s]); \
        } \
    } }

// ---------------- conv2 + relu + maxpool2 + gate-logit partials ----------------
// 192 threads; static smem (R10 champion shape); occupancy target raised to 4 CTAs/SM
__global__ __launch_bounds__(192, 4) void conv2pool_kernel(const float* __restrict__ bias,
                                                           const float* __restrict__ wg1) {
    __shared__ float sin[6272];
    __shared__ float sw[4608];
    float (*sred)[8] = (float(*)[8])sin;

    int n = blockIdx.y;
    int oc0 = blockIdx.x * 16;
    int tid = threadIdx.x;

    const float4* wsrc = (const float4*)&g_wt[blockIdx.x * 4608];
    for (int i = tid; i < 1152; i += 192) ((float4*)sw)[i] = wsrc[i];

    ull acc[8][4];
#pragma unroll
    for (int p = 0; p < 8; p++)
#pragma unroll
        for (int q = 0; q < 4; q++) acc[p][q] = 0ull;

    bool active = tid < 169;
    int pi = active ? tid / 13 : 0;
    int pj = active ? tid % 13 : 0;
    int row0 = (2*pi)*28 + 2*pj;

    const float4* h1base = (const float4*)(g_h1 + (size_t)n*32*784);

    for (int icc = 0; icc < 4; icc++) {
        __syncthreads();
        const float4* src = h1base + (size_t)icc*1568;
        for (int i = tid; i < 1568; i += 192) ((float4*)sin)[i] = src[i];
        __syncthreads();
        if (active) {
#pragma unroll
            for (int ic = 0; ic < 8; ic++) {
                const float* srow = &sin[ic*784 + row0];
                int woff = (icc*8 + ic)*144;
                ull pa[4], pb[4];
                LOAD_DUP(pa, srow);
                LOAD_DUP(pb, srow + 28);
                ROW_TAPS(0, pa, pb);
                LOAD_DUP(pa, srow + 56);
                ROW_TAPS(1, pb, pa);
                LOAD_DUP(pb, srow + 84);
                ROW_TAPS(2, pa, pb);
            }
        }
    }

    float part[8];
#pragma unroll
    for (int e = 0; e < 8; e++) part[e] = 0.f;

    if (active) {
#pragma unroll
        for (int p = 0; p < 8; p++) {
            float2 v0 = f32x2_unpack(acc[p][0]);
            float2 v1 = f32x2_unpack(acc[p][1]);
            float2 v2 = f32x2_unpack(acc[p][2]);
            float2 v3 = f32x2_unpack(acc[p][3]);
            float mlo = fmaxf(fmaxf(v0.x, v1.x), fmaxf(v2.x, v3.x)) + bias[oc0 + 2*p];
            float mhi = fmaxf(fmaxf(v0.y, v1.y), fmaxf(v2.y, v3.y)) + bias[oc0 + 2*p + 1];
            mlo = fmaxf(mlo, 0.f);
            mhi = fmaxf(mhi, 0.f);
            int flo = (oc0 + 2*p)*169 + tid;
            int fhi = flo + 169;
            g_h2[(size_t)n*D1 + flo] = mlo;
            g_h2[(size_t)n*D1 + fhi] = mhi;
            const float4* wlo = (const float4*)(wg1 + (size_t)flo*8);
            const float4* whi = (const float4*)(wg1 + (size_t)fhi*8);
            float4 a0 = wlo[0], a1 = wlo[1], b0 = whi[0], b1 = whi[1];
            part[0] = fmaf(mlo, a0.x, fmaf(mhi, b0.x, part[0]));
            part[1] = fmaf(mlo, a0.y, fmaf(mhi, b0.y, part[1]));
            part[2] = fmaf(mlo, a0.z, fmaf(mhi, b0.z, part[2]));
            part[3] = fmaf(mlo, a0.w, fmaf(mhi, b0.w, part[3]));
            part[4] = fmaf(mlo, a1.x, fmaf(mhi, b1.x, part[4]));
            part[5] = fmaf(mlo, a1.y, fmaf(mhi, b1.y, part[5]));
            part[6] = fmaf(mlo, a1.z, fmaf(mhi, b1.z, part[6]));
            part[7] = fmaf(mlo, a1.w, fmaf(mhi, b1.w, part[7]));
        }
    }

    __syncthreads();
#pragma unroll
    for (int e = 0; e < 8; e++) sred[tid][e] = part[e];
    if (tid < 64)
#pragma unroll
        for (int e = 0; e < 8; e++) sred[192 + tid][e] = 0.f;
    __syncthreads();
    for (int off = 128; off > 0; off >>= 1) {
        if (tid < off) {
            float4* d = (float4*)sred[tid];
            const float4* s = (const float4*)sred[tid + off];
            float4 d0 = d[0], d1 = d[1], s0 = s[0], s1 = s[1];
            d0.x += s0.x; d0.y += s0.y; d0.z += s0.z; d0.w += s0.w;
            d1.x += s1.x; d1.y += s1.y; d1.z += s1.z; d1.w += s1.w;
            d[0] = d0; d[1] = d1;
        }
        __syncthreads();
    }
    if (tid < 8)
        g_lpart[((size_t)blockIdx.x*BATCH + n)*8 + tid] = sred[0][tid];
}

// ---------------- top-2 + gates + expert dispatch ----------------
__global__ void top2_kernel(float* __restrict__ out_g1) {
    int b = blockIdx.x*blockDim.x + threadIdx.x;
    if (b >= BATCH) return;
    float v[8];
#pragma unroll
    for (int e = 0; e < 8; e++) v[e] = 0.f;
#pragma unroll
    for (int g = 0; g < 4; g++) {
        const float4* p = (const float4*)&g_lpart[((size_t)g*BATCH + b)*8];
        float4 a = p[0], c = p[1];
        v[0] += a.x; v[1] += a.y; v[2] += a.z; v[3] += a.w;
        v[4] += c.x; v[5] += c.y; v[6] += c.z; v[7] += c.w;
    }
    int i0 = 0; float v0 = v[0];
#pragma unroll
    for (int e = 1; e < 8; e++) if (v[e] > v0) { v0 = v[e]; i0 = e; }
    int i1 = -1; float v1 = -1e30f;
#pragma unroll
    for (int e = 0; e < 8; e++) if (e != i0 && v[e] > v1) { v1 = v[e]; i1 = e; }
    float t = expf(v1 - v0);
    float inv = 1.f / (1.f + t);
    float g0 = inv, g1 = t * inv;
#pragma unroll
    for (int e = 0; e < 8; e++)
        out_g1[b*8+e] = (e == i0) ? g0 : ((e == i1) ? g1 : 0.f);
    int p0 = atomicAdd(&g_cnt[i0], 1);
    g_tok[i0*BATCH+p0] = b; g_gate[i0*BATCH+p0] = g0; g_slot[i0*BATCH+p0] = 0;
    int p1 = atomicAdd(&g_cnt[i1], 1);
    g_tok[i1*BATCH+p1] = b; g_gate[i1*BATCH+p1] = g1; g_slot[i1*BATCH+p1] = 1;
}

// ---------------- expert GEMM, f32x2, double buffer, split-K x2 ----------------
__global__ __launch_bounds__(256) void expert_gemm_kernel(const float* __restrict__ W1,
                                                          const float* __restrict__ b1) {
    int e = blockIdx.y;
    int kh = blockIdx.z;
    int cnt = g_cnt[e];
    int m0 = blockIdx.x * 64;
    if (m0 >= cnt) return;
    int tid = threadIdx.x, tx = tid & 31, ty = tid >> 5;
    __shared__ float As[2][16][64];
    __shared__ float Bs[2][16][128];
    int ar = tid >> 2, akq = tid & 3;
    int lrc = min(m0 + ar, cnt - 1);
    int ltok = g_tok[e*BATCH + lrc];
    const float* arow = g_h2 + (size_t)ltok*D1 + kh*KSPLIT + akq*4;
    const float* bbase = W1 + (size_t)e*D1*128 + (size_t)kh*KSPLIT*128;
    int br0 = tid >> 5, bc0 = tid & 31, br1 = br0 + 8;
    {
        float4 av = *(const float4*)(arow);
        float4 bv0 = *(const float4*)(bbase + (size_t)br0*128 + bc0*4);
        float4 bv1 = *(const float4*)(bbase + (size_t)br1*128 + bc0*4);
        As[0][akq*4+0][ar] = av.x; As[0][akq*4+1][ar] = av.y;
        As[0][akq*4+2][ar] = av.z; As[0][akq*4+3][ar] = av.w;
        *(float4*)&Bs[0][br0][bc0*4] = bv0;
        *(float4*)&Bs[0][br1][bc0*4] = bv1;
    }
    __syncthreads();
    ull acc[4][4];
#pragma unroll
    for (int i = 0; i < 4; i++)
#pragma unroll
        for (int j = 0; j < 4; j++) acc[i][j] = 0ull;
    int cur = 0;
    for (int k0 = 0; k0 < KSPLIT; k0 += 16) {
        bool more = (k0 + 16) < KSPLIT;
        float4 nav, nbv0, nbv1;
        if (more) {
            nav  = *(const float4*)(arow + k0 + 16);
            nbv0 = *(const float4*)(bbase + (size_t)(k0+16+br0)*128 + bc0*4);
            nbv1 = *(const float4*)(bbase + (size_t)(k0+16+br1)*128 + bc0*4);
        }
#pragma unroll
        for (int k = 0; k < 16; k++) {
            float4 bf = *(const float4*)&Bs[cur][k][tx*4];
            ull bd0 = f32x2_dup(bf.x), bd1 = f32x2_dup(bf.y);
            ull bd2 = f32x2_dup(bf.z), bd3 = f32x2_dup(bf.w);
            const ull* ap = (const ull*)&As[cur][k][ty*8];
#pragma unroll
            for (int ip = 0; ip < 4; ip++) {
                ull a2 = ap[ip];
                acc[ip][0] = f32x2_fma(a2, bd0, acc[ip][0]);
                acc[ip][1] = f32x2_fma(a2, bd1, acc[ip][1]);
                acc[ip][2] = f32x2_fma(a2, bd2, acc[ip][2]);
                acc[ip][3] = f32x2_fma(a2, bd3, acc[ip][3]);
            }
        }
        if (more) {
            int nxt = cur ^ 1;
            As[nxt][akq*4+0][ar] = nav.x; As[nxt][akq*4+1][ar] = nav.y;
            As[nxt][akq*4+2][ar] = nav.z; As[nxt][akq*4+3][ar] = nav.w;
            *(float4*)&Bs[nxt][br0][bc0*4] = nbv0;
            *(float4*)&Bs[nxt][br1][bc0*4] = nbv1;
        }
        __syncthreads();
        cur ^= 1;
    }
    float bb[4];
#pragma unroll
    for (int j = 0; j < 4; j++) bb[j] = (kh == 0) ? b1[e*128 + tx*4 + j] : 0.f;
#pragma unroll
    for (int ip = 0; ip < 4; ip++) {
        float2 p0 = f32x2_unpack(acc[ip][0]);
        float2 p1 = f32x2_unpack(acc[ip][1]);
        float2 p2 = f32x2_unpack(acc[ip][2]);
        float2 p3 = f32x2_unpack(acc[ip][3]);
        int r0 = m0 + ty*8 + 2*ip, r1 = r0 + 1;
        if (r0 < cnt) {
            int tok = g_tok[e*BATCH + r0];
            float gt = g_gate[e*BATCH + r0];
            int sl = g_slot[e*BATCH + r0]*2 + kh;
            float* yp = g_ypart + ((size_t)sl*BATCH + tok)*128 + tx*4;
            yp[0] = gt*(p0.x+bb[0]); yp[1] = gt*(p1.x+bb[1]);
            yp[2] = gt*(p2.x+bb[2]); yp[3] = gt*(p3.x+bb[3]);
        }
        if (r1 < cnt) {
            int tok = g_tok[e*BATCH + r1];
            float gt = g_gate[e*BATCH + r1];
            int sl = g_slot[e*BATCH + r1]*2 + kh;
            float* yp = g_ypart + ((size_t)sl*BATCH + tok)*128 + tx*4;
            yp[0] = gt*(p0.y+bb[0]); yp[1] = gt*(p1.y+bb[1]);
            yp[2] = gt*(p2.y+bb[2]); yp[3] = gt*(p3.y+bb[3]);
        }
    }
}

// ---------------- MoE layer 2 + log_softmax ----------------
__global__ void moe2_kernel(const float* __restrict__ wg2, const float* __restrict__ W2,
                            const float* __restrict__ b2, float* __restrict__ out) {
    int warp = (blockIdx.x*blockDim.x + threadIdx.x) >> 5;
    int lane = threadIdx.x & 31;
    if (warp >= BATCH) return;
    int b = warp;
    float h[4];
#pragma unroll
    for (int q = 0; q < 4; q++) {
        int k = q*32 + lane;
        float v = g_ypart[(size_t)b*128 + k]
                + g_ypart[((size_t)BATCH + b)*128 + k]
                + g_ypart[((size_t)2*BATCH + b)*128 + k]
                + g_ypart[((size_t)3*BATCH + b)*128 + k];
        h[q] = fmaxf(v, 0.f);
    }
    float lg[8];
#pragma unroll
    for (int e = 0; e < 8; e++) {
        float p = 0.f;
#pragma unroll
        for (int q = 0; q < 4; q++) p = fmaf(h[q], wg2[(q*32+lane)*8 + e], p);
#pragma unroll
        for (int off = 16; off > 0; off >>= 1) p += __shfl_xor_sync(0xffffffffu, p, off);
        lg[e] = p;
    }
    int i0 = 0; float v0 = lg[0];
#pragma unroll
    for (int e = 1; e < 8; e++) if (lg[e] > v0) { v0 = lg[e]; i0 = e; }
    int i1 = -1; float v1 = -1e30f;
#pragma unroll
    for (int e = 0; e < 8; e++) if (e != i0 && lg[e] > v1) { v1 = lg[e]; i1 = e; }
    float t = expf(v1 - v0);
    float inv = 1.f / (1.f + t);
    float g0 = inv, g1 = t * inv;
    if (lane < 8)
        out[G2_OFF + b*8 + lane] = (lane == i0) ? g0 : ((lane == i1) ? g1 : 0.f);
    float oj[10];
#pragma unroll
    for (int j = 0; j < 10; j++) {
        float p = 0.f;
#pragma unroll
        for (int q = 0; q < 4; q++) {
            int k = q*32 + lane;
            p = fmaf(h[q], g0*W2[(i0*128 + k)*10 + j] + g1*W2[(i1*128 + k)*10 + j], p);
        }
#pragma unroll
        for (int off = 16; off > 0; off >>= 1) p += __shfl_xor_sync(0xffffffffu, p, off);
        oj[j] = p + g0*b2[i0*10 + j] + g1*b2[i1*10 + j];
    }
    float m = oj[0];
#pragma unroll
    for (int j = 1; j < 10; j++) m = fmaxf(m, oj[j]);
    float s = 0.f;
#pragma unroll
    for (int j = 0; j < 10; j++) s += expf(oj[j] - m);
    float lse = logf(s);
#pragma unroll
    for (int j = 0; j < 10; j++)
        if (lane == j) out[b*10 + j] = oj[j] - m - lse;
}

// ---------------- loss ----------------
__global__ void loss_kernel(float* __restrict__ out) {
    const float* g1p = out + G1_OFF;
    const float* g2p = out + G2_OFF;
    int tid = threadIdx.x;
    float a[4][8];
#pragma unroll
    for (int t = 0; t < 4; t++)
#pragma unroll
        for (int e = 0; e < 8; e++) a[t][e] = 0.f;
    for (int b = tid; b < BATCH; b += 256) {
#pragma unroll
        for (int e = 0; e < 8; e++) {
            float g = g1p[b*8+e];
            a[0][e] += g; a[1][e] += (g > 0.f) ? 1.f : 0.f;
            float g2 = g2p[b*8+e];
            a[2][e] += g2; a[3][e] += (g2 > 0.f) ? 1.f : 0.f;
        }
    }
    __shared__ float s[256][33];
#pragma unroll
    for (int t = 0; t < 4; t++)
#pragma unroll
        for (int e = 0; e < 8; e++) s[tid][t*8+e] = a[t][e];
    __syncthreads();
    for (int off = 128; off > 0; off >>= 1) {
        if (tid < off)
            for (int i = 0; i < 32; i++) s[tid][i] += s[tid+off][i];
        __syncthreads();
    }
    if (tid == 0) {
        float loss = 0.f;
        for (int t = 0; t < 4; t++) {
            float sum = 0.f;
            for (int e = 0; e < 8; e++) sum += s[0][t*8+e];
            float mean = sum / 8.f;
            float var = 0.f;
            for (int e = 0; e < 8; e++) { float d = s[0][t*8+e] - mean; var += d*d; }
            var /= 7.f;
            loss += var / (mean*mean + 1e-10f);
        }
        out[LOSS_OFF] = loss * 3e-5f;
    }
}

// ---------------- launch ----------------
extern "C" void kernel_launch(void* const* d_in, const int* in_sizes, int n_in,
                              void* d_out, int out_size) {
    const float* x    = (const float*)d_in[0];
    const float* c1w  = (const float*)d_in[1];
    const float* c1b  = (const float*)d_in[2];
    const float* c2w  = (const float*)d_in[3];
    const float* c2b  = (const float*)d_in[4];
    const float* wg1  = (const float*)d_in[5];
    const float* W1   = (const float*)d_in[6];
    const float* b1   = (const float*)d_in[7];
    const float* wg2  = (const float*)d_in[8];
    const float* W2   = (const float*)d_in[9];
    const float* b2   = (const float*)d_in[10];
    float* out = (float*)d_out;

    init_transpose_kernel<<<72, 256>>>(c2w);
    conv1_kernel<<<BATCH, 256>>>(x, c1w, c1b);
    dummy_kernel<<<1, 32>>>();                 // keeps conv2pool in the profiled slot
    conv2pool_kernel<<<dim3(4, BATCH), 192>>>(c2b, wg1);
    top2_kernel<<<16, 256>>>(out + G1_OFF);
    expert_gemm_kernel<<<dim3(64, NEXP, 2), 256>>>(W1, b1);
    moe2_kernel<<<512, 256>>>(wg2, W2, b2, out);
    loss_kernel<<<1, 256>>>(out);
}

// round 14
// speedup vs baseline: 1.3451x; 1.3451x over previous
#include <cuda_runtime.h>
#include <math.h>

#define BATCH 4096
#define D1 10816
#define D2 128
#define NEXP 8
#define KSPLIT 5408

#define G1_OFF (BATCH*10)
#define G2_OFF (G1_OFF + BATCH*8)
#define LOSS_OFF (G2_OFF + BATCH*8)

typedef unsigned long long ull;

__device__ __forceinline__ ull f32x2_fma(ull a, ull b, ull c) {
    ull d; asm("fma.rn.f32x2 %0, %1, %2, %3;" : "=l"(d) : "l"(a), "l"(b), "l"(c)); return d;
}
__device__ __forceinline__ ull f32x2_dup(float x) {
    ull d; asm("mov.b64 %0, {%1, %1};" : "=l"(d) : "f"(x)); return d;
}
__device__ __forceinline__ float2 f32x2_unpack(ull v) {
    float2 r; asm("mov.b64 {%0, %1}, %2;" : "=f"(r.x), "=f"(r.y) : "l"(v)); return r;
}

// ---------------- scratch ----------------
__device__ float g_h1[(size_t)BATCH*32*28*28];
__device__ float g_h2[(size_t)BATCH*D1];
__device__ float g_lpart[(size_t)4*BATCH*8];
__device__ float g_wt[64*288];
__device__ int   g_cnt[NEXP];
__device__ int   g_tok[NEXP*BATCH];
__device__ float g_gate[NEXP*BATCH];
__device__ int   g_slot[NEXP*BATCH];
__device__ float g_ypart[(size_t)4*BATCH*D2];   // [2*dispatch_slot + khalf]

// ---------------- init + conv2 weight transpose ----------------
__global__ void init_transpose_kernel(const float* __restrict__ w) {
    int idx = blockIdx.x*256 + threadIdx.x;
    if (idx < NEXP) g_cnt[idx] = 0;
    if (idx < 64*288) {
        int ocl = idx & 15;
        int r = idx >> 4;
        int tap = r % 9;
        int r2 = r / 9;
        int ic = r2 & 31;
        int ocg = r2 >> 5;
        g_wt[idx] = w[(ocg*16 + ocl)*288 + ic*9 + tap];
    }
}

// ---------------- conv1 + relu ----------------
__global__ void conv1_kernel(const float* __restrict__ x,
                             const float* __restrict__ w,
                             const float* __restrict__ b) {
    __shared__ float sw[288], sb[32];
    int n = blockIdx.x, tid = threadIdx.x;
    for (int i = tid; i < 288; i += blockDim.x) sw[i] = w[i];
    if (tid < 32) sb[tid] = b[tid];
    __syncthreads();
    const float* xr = x + (size_t)n * 900;
    for (int pos = tid; pos < 784; pos += blockDim.x) {
        int i = pos / 28, j = pos % 28;
        float p[9];
#pragma unroll
        for (int a = 0; a < 3; a++)
#pragma unroll
            for (int c = 0; c < 3; c++) p[a*3+c] = xr[(i+a)*30 + j + c];
#pragma unroll
        for (int oc = 0; oc < 32; oc++) {
            float v = sb[oc];
#pragma unroll
            for (int t = 0; t < 9; t++) v = fmaf(p[t], sw[oc*9+t], v);
            g_h1[((size_t)n*32 + oc)*784 + pos] = fmaxf(v, 0.f);
        }
    }
}

// dup 4 consecutive input pixels into f32x2 regs
#define LOAD_DUP(dst, p) { \
    float2 _u0 = *(const float2*)(p); \
    float2 _u1 = *(const float2*)((p)+2); \
    dst[0] = f32x2_dup(_u0.x); dst[1] = f32x2_dup(_u0.y); \
    dst[2] = f32x2_dup(_u1.x); dst[3] = f32x2_dup(_u1.y); }

// process taps (3a+0..2) using row-pair (rlo = conv row a, rhi = conv row a+1)
#define ROW_TAPS(a, rlo, rhi) { \
_Pragma("unroll") \
    for (int c = 0; c < 3; c++) { \
        const ulonglong2* _w = (const ulonglong2*)&sw[((3*(a)+c)*16) + woff]; \
        ulonglong2 wA = _w[0], wB = _w[1], wC = _w[2], wD = _w[3]; \
_Pragma("unroll") \
        for (int s = 0; s < 2; s++) { \
            ull p0 = rlo[c+s], p1 = rhi[c+s]; \
            acc[0][s]   = f32x2_fma(wA.x, p0, acc[0][s]); \
            acc[1][s]   = f32x2_fma(wA.y, p0, acc[1][s]); \
            acc[2][s]   = f32x2_fma(wB.x, p0, acc[2][s]); \
            acc[3][s]   = f32x2_fma(wB.y, p0, acc[3][s]); \
            acc[4][s]   = f32x2_fma(wC.x, p0, acc[4][s]); \
            acc[5][s]   = f32x2_fma(wC.y, p0, acc[5][s]); \
            acc[6][s]   = f32x2_fma(wD.x, p0, acc[6][s]); \
            acc[7][s]   = f32x2_fma(wD.y, p0, acc[7][s]); \
            acc[0][2+s] = f32x2_fma(wA.x, p1, acc[0][2+s]); \
            acc[1][2+s] = f32x2_fma(wA.y, p1, acc[1][2+s]); \
            acc[2][2+s] = f32x2_fma(wB.x, p1, acc[2][2+s]); \
            acc[3][2+s] = f32x2_fma(wB.y, p1, acc[3][2+s]); \
            acc[4][2+s] = f32x2_fma(wC.x, p1, acc[4][2+s]); \
            acc[5][2+s] = f32x2_fma(wC.y, p1, acc[5][2+s]); \
            acc[6][2+s] = f32x2_fma(wD.x, p1, acc[6][2+s]); \
            acc[7][2+s] = f32x2_fma(wD.y, p1, acc[7][2+s]); \
        } \
    } }

// ---------------- conv2 + relu + maxpool2 + gate-logit partials ----------------
// block (ocg16, n): 192 threads, 169 active; 16 oc via 8 f32x2 pairs; 3 CTAs/SM
__global__ __launch_bounds__(192, 3) void conv2pool_kernel(const float* __restrict__ bias,
                                                           const float* __restrict__ wg1) {
    __shared__ float sin[6272];
    __shared__ float sw[4608];
    float (*sred)[8] = (float(*)[8])sin;

    int n = blockIdx.y;
    int oc0 = blockIdx.x * 16;
    int tid = threadIdx.x;

    const float4* wsrc = (const float4*)&g_wt[blockIdx.x * 4608];
    for (int i = tid; i < 1152; i += 192) ((float4*)sw)[i] = wsrc[i];

    ull acc[8][4];
#pragma unroll
    for (int p = 0; p < 8; p++)
#pragma unroll
        for (int q = 0; q < 4; q++) acc[p][q] = 0ull;

    bool active = tid < 169;
    int pi = active ? tid / 13 : 0;
    int pj = active ? tid % 13 : 0;
    int row0 = (2*pi)*28 + 2*pj;

    const float4* h1base = (const float4*)(g_h1 + (size_t)n*32*784);

    for (int icc = 0; icc < 4; icc++) {
        __syncthreads();
        const float4* src = h1base + (size_t)icc*1568;
        for (int i = tid; i < 1568; i += 192) ((float4*)sin)[i] = src[i];
        __syncthreads();
        if (active) {
#pragma unroll
            for (int ic = 0; ic < 8; ic++) {
                const float* srow = &sin[ic*784 + row0];
                int woff = (icc*8 + ic)*144;
                ull pa[4], pb[4];
                LOAD_DUP(pa, srow);
                LOAD_DUP(pb, srow + 28);
                ROW_TAPS(0, pa, pb);
                LOAD_DUP(pa, srow + 56);
                ROW_TAPS(1, pb, pa);
                LOAD_DUP(pb, srow + 84);
                ROW_TAPS(2, pa, pb);
            }
        }
    }

    float part[8];
#pragma unroll
    for (int e = 0; e < 8; e++) part[e] = 0.f;

    if (active) {
#pragma unroll
        for (int p = 0; p < 8; p++) {
            float2 v0 = f32x2_unpack(acc[p][0]);
            float2 v1 = f32x2_unpack(acc[p][1]);
            float2 v2 = f32x2_unpack(acc[p][2]);
            float2 v3 = f32x2_unpack(acc[p][3]);
            float mlo = fmaxf(fmaxf(v0.x, v1.x), fmaxf(v2.x, v3.x)) + bias[oc0 + 2*p];
            float mhi = fmaxf(fmaxf(v0.y, v1.y), fmaxf(v2.y, v3.y)) + bias[oc0 + 2*p + 1];
            mlo = fmaxf(mlo, 0.f);
            mhi = fmaxf(mhi, 0.f);
            int flo = (oc0 + 2*p)*169 + tid;
            int fhi = flo + 169;
            g_h2[(size_t)n*D1 + flo] = mlo;
            g_h2[(size_t)n*D1 + fhi] = mhi;
            const float4* wlo = (const float4*)(wg1 + (size_t)flo*8);
            const float4* whi = (const float4*)(wg1 + (size_t)fhi*8);
            float4 a0 = wlo[0], a1 = wlo[1], b0 = whi[0], b1 = whi[1];
            part[0] = fmaf(mlo, a0.x, fmaf(mhi, b0.x, part[0]));
            part[1] = fmaf(mlo, a0.y, fmaf(mhi, b0.y, part[1]));
            part[2] = fmaf(mlo, a0.z, fmaf(mhi, b0.z, part[2]));
            part[3] = fmaf(mlo, a0.w, fmaf(mhi, b0.w, part[3]));
            part[4] = fmaf(mlo, a1.x, fmaf(mhi, b1.x, part[4]));
            part[5] = fmaf(mlo, a1.y, fmaf(mhi, b1.y, part[5]));
            part[6] = fmaf(mlo, a1.z, fmaf(mhi, b1.z, part[6]));
            part[7] = fmaf(mlo, a1.w, fmaf(mhi, b1.w, part[7]));
        }
    }

    __syncthreads();
#pragma unroll
    for (int e = 0; e < 8; e++) sred[tid][e] = part[e];
    if (tid < 64)
#pragma unroll
        for (int e = 0; e < 8; e++) sred[192 + tid][e] = 0.f;
    __syncthreads();
    for (int off = 128; off > 0; off >>= 1) {
        if (tid < off) {
            float4* d = (float4*)sred[tid];
            const float4* s = (const float4*)sred[tid + off];
            float4 d0 = d[0], d1 = d[1], s0 = s[0], s1 = s[1];
            d0.x += s0.x; d0.y += s0.y; d0.z += s0.z; d0.w += s0.w;
            d1.x += s1.x; d1.y += s1.y; d1.z += s1.z; d1.w += s1.w;
            d[0] = d0; d[1] = d1;
        }
        __syncthreads();
    }
    if (tid < 8)
        g_lpart[((size_t)blockIdx.x*BATCH + n)*8 + tid] = sred[0][tid];
}

// ---------------- top-2 + gates + expert dispatch ----------------
__global__ void top2_kernel(float* __restrict__ out_g1) {
    int b = blockIdx.x*blockDim.x + threadIdx.x;
    if (b >= BATCH) return;
    float v[8];
#pragma unroll
    for (int e = 0; e < 8; e++) v[e] = 0.f;
#pragma unroll
    for (int g = 0; g < 4; g++) {
        const float4* p = (const float4*)&g_lpart[((size_t)g*BATCH + b)*8];
        float4 a = p[0], c = p[1];
        v[0] += a.x; v[1] += a.y; v[2] += a.z; v[3] += a.w;
        v[4] += c.x; v[5] += c.y; v[6] += c.z; v[7] += c.w;
    }
    int i0 = 0; float v0 = v[0];
#pragma unroll
    for (int e = 1; e < 8; e++) if (v[e] > v0) { v0 = v[e]; i0 = e; }
    int i1 = -1; float v1 = -1e30f;
#pragma unroll
    for (int e = 0; e < 8; e++) if (e != i0 && v[e] > v1) { v1 = v[e]; i1 = e; }
    float t = expf(v1 - v0);
    float inv = 1.f / (1.f + t);
    float g0 = inv, g1 = t * inv;
#pragma unroll
    for (int e = 0; e < 8; e++)
        out_g1[b*8+e] = (e == i0) ? g0 : ((e == i1) ? g1 : 0.f);
    int p0 = atomicAdd(&g_cnt[i0], 1);
    g_tok[i0*BATCH+p0] = b; g_gate[i0*BATCH+p0] = g0; g_slot[i0*BATCH+p0] = 0;
    int p1 = atomicAdd(&g_cnt[i1], 1);
    g_tok[i1*BATCH+p1] = b; g_gate[i1*BATCH+p1] = g1; g_slot[i1*BATCH+p1] = 1;
}

// ---------------- expert GEMM, f32x2, double buffer, split-K x2 ----------------
__global__ __launch_bounds__(256) void expert_gemm_kernel(const float* __restrict__ W1,
                                                          const float* __restrict__ b1) {
    int e = blockIdx.y;
    int kh = blockIdx.z;
    int cnt = g_cnt[e];
    int m0 = blockIdx.x * 64;
    if (m0 >= cnt) return;
    int tid = threadIdx.x, tx = tid & 31, ty = tid >> 5;
    __shared__ float As[2][16][64];
    __shared__ float Bs[2][16][128];
    int ar = tid >> 2, akq = tid & 3;
    int lrc = min(m0 + ar, cnt - 1);
    int ltok = g_tok[e*BATCH + lrc];
    const float* arow = g_h2 + (size_t)ltok*D1 + kh*KSPLIT + akq*4;
    const float* bbase = W1 + (size_t)e*D1*128 + (size_t)kh*KSPLIT*128;
    int br0 = tid >> 5, bc0 = tid & 31, br1 = br0 + 8;
    {
        float4 av = *(const float4*)(arow);
        float4 bv0 = *(const float4*)(bbase + (size_t)br0*128 + bc0*4);
        float4 bv1 = *(const float4*)(bbase + (size_t)br1*128 + bc0*4);
        As[0][akq*4+0][ar] = av.x; As[0][akq*4+1][ar] = av.y;
        As[0][akq*4+2][ar] = av.z; As[0][akq*4+3][ar] = av.w;
        *(float4*)&Bs[0][br0][bc0*4] = bv0;
        *(float4*)&Bs[0][br1][bc0*4] = bv1;
    }
    __syncthreads();
    ull acc[4][4];
#pragma unroll
    for (int i = 0; i < 4; i++)
#pragma unroll
        for (int j = 0; j < 4; j++) acc[i][j] = 0ull;
    int cur = 0;
    for (int k0 = 0; k0 < KSPLIT; k0 += 16) {
        bool more = (k0 + 16) < KSPLIT;
        float4 nav, nbv0, nbv1;
        if (more) {
            nav  = *(const float4*)(arow + k0 + 16);
            nbv0 = *(const float4*)(bbase + (size_t)(k0+16+br0)*128 + bc0*4);
            nbv1 = *(const float4*)(bbase + (size_t)(k0+16+br1)*128 + bc0*4);
        }
#pragma unroll
        for (int k = 0; k < 16; k++) {
            float4 bf = *(const float4*)&Bs[cur][k][tx*4];
            ull bd0 = f32x2_dup(bf.x), bd1 = f32x2_dup(bf.y);
            ull bd2 = f32x2_dup(bf.z), bd3 = f32x2_dup(bf.w);
            const ull* ap = (const ull*)&As[cur][k][ty*8];
#pragma unroll
            for (int ip = 0; ip < 4; ip++) {
                ull a2 = ap[ip];
                acc[ip][0] = f32x2_fma(a2, bd0, acc[ip][0]);
                acc[ip][1] = f32x2_fma(a2, bd1, acc[ip][1]);
                acc[ip][2] = f32x2_fma(a2, bd2, acc[ip][2]);
                acc[ip][3] = f32x2_fma(a2, bd3, acc[ip][3]);
            }
        }
        if (more) {
            int nxt = cur ^ 1;
            As[nxt][akq*4+0][ar] = nav.x; As[nxt][akq*4+1][ar] = nav.y;
            As[nxt][akq*4+2][ar] = nav.z; As[nxt][akq*4+3][ar] = nav.w;
            *(float4*)&Bs[nxt][br0][bc0*4] = nbv0;
            *(float4*)&Bs[nxt][br1][bc0*4] = nbv1;
        }
        __syncthreads();
        cur ^= 1;
    }
    float bb[4];
#pragma unroll
    for (int j = 0; j < 4; j++) bb[j] = (kh == 0) ? b1[e*128 + tx*4 + j] : 0.f;
#pragma unroll
    for (int ip = 0; ip < 4; ip++) {
        float2 p0 = f32x2_unpack(acc[ip][0]);
        float2 p1 = f32x2_unpack(acc[ip][1]);
        float2 p2 = f32x2_unpack(acc[ip][2]);
        float2 p3 = f32x2_unpack(acc[ip][3]);
        int r0 = m0 + ty*8 + 2*ip, r1 = r0 + 1;
        if (r0 < cnt) {
            int tok = g_tok[e*BATCH + r0];
            float gt = g_gate[e*BATCH + r0];
            int sl = g_slot[e*BATCH + r0]*2 + kh;
            float* yp = g_ypart + ((size_t)sl*BATCH + tok)*128 + tx*4;
            yp[0] = gt*(p0.x+bb[0]); yp[1] = gt*(p1.x+bb[1]);
            yp[2] = gt*(p2.x+bb[2]); yp[3] = gt*(p3.x+bb[3]);
        }
        if (r1 < cnt) {
            int tok = g_tok[e*BATCH + r1];
            float gt = g_gate[e*BATCH + r1];
            int sl = g_slot[e*BATCH + r1]*2 + kh;
            float* yp = g_ypart + ((size_t)sl*BATCH + tok)*128 + tx*4;
            yp[0] = gt*(p0.y+bb[0]); yp[1] = gt*(p1.y+bb[1]);
            yp[2] = gt*(p2.y+bb[2]); yp[3] = gt*(p3.y+bb[3]);
        }
    }
}

// ---------------- MoE layer 2 + log_softmax ----------------
__global__ void moe2_kernel(const float* __restrict__ wg2, const float* __restrict__ W2,
                            const float* __restrict__ b2, float* __restrict__ out) {
    int warp = (blockIdx.x*blockDim.x + threadIdx.x) >> 5;
    int lane = threadIdx.x & 31;
    if (warp >= BATCH) return;
    int b = warp;
    float h[4];
#pragma unroll
    for (int q = 0; q < 4; q++) {
        int k = q*32 + lane;
        float v = g_ypart[(size_t)b*128 + k]
                + g_ypart[((size_t)BATCH + b)*128 + k]
                + g_ypart[((size_t)2*BATCH + b)*128 + k]
                + g_ypart[((size_t)3*BATCH + b)*128 + k];
        h[q] = fmaxf(v, 0.f);
    }
    float lg[8];
#pragma unroll
    for (int e = 0; e < 8; e++) {
        float p = 0.f;
#pragma unroll
        for (int q = 0; q < 4; q++) p = fmaf(h[q], wg2[(q*32+lane)*8 + e], p);
#pragma unroll
        for (int off = 16; off > 0; off >>= 1) p += __shfl_xor_sync(0xffffffffu, p, off);
        lg[e] = p;
    }
    int i0 = 0; float v0 = lg[0];
#pragma unroll
    for (int e = 1; e < 8; e++) if (lg[e] > v0) { v0 = lg[e]; i0 = e; }
    int i1 = -1; float v1 = -1e30f;
#pragma unroll
    for (int e = 0; e < 8; e++) if (e != i0 && lg[e] > v1) { v1 = lg[e]; i1 = e; }
    float t = expf(v1 - v0);
    float inv = 1.f / (1.f + t);
    float g0 = inv, g1 = t * inv;
    if (lane < 8)
        out[G2_OFF + b*8 + lane] = (lane == i0) ? g0 : ((lane == i1) ? g1 : 0.f);
    float oj[10];
#pragma unroll
    for (int j = 0; j < 10; j++) {
        float p = 0.f;
#pragma unroll
        for (int q = 0; q < 4; q++) {
            int k = q*32 + lane;
            p = fmaf(h[q], g0*W2[(i0*128 + k)*10 + j] + g1*W2[(i1*128 + k)*10 + j], p);
        }
#pragma unroll
        for (int off = 16; off > 0; off >>= 1) p += __shfl_xor_sync(0xffffffffu, p, off);
        oj[j] = p + g0*b2[i0*10 + j] + g1*b2[i1*10 + j];
    }
    float m = oj[0];
#pragma unroll
    for (int j = 1; j < 10; j++) m = fmaxf(m, oj[j]);
    float s = 0.f;
#pragma unroll
    for (int j = 0; j < 10; j++) s += expf(oj[j] - m);
    float lse = logf(s);
#pragma unroll
    for (int j = 0; j < 10; j++)
        if (lane == j) out[b*10 + j] = oj[j] - m - lse;
}

// ---------------- loss ----------------
__global__ void loss_kernel(float* __restrict__ out) {
    const float* g1p = out + G1_OFF;
    const float* g2p = out + G2_OFF;
    int tid = threadIdx.x;
    float a[4][8];
#pragma unroll
    for (int t = 0; t < 4; t++)
#pragma unroll
        for (int e = 0; e < 8; e++) a[t][e] = 0.f;
    for (int b = tid; b < BATCH; b += 256) {
#pragma unroll
        for (int e = 0; e < 8; e++) {
            float g = g1p[b*8+e];
            a[0][e] += g; a[1][e] += (g > 0.f) ? 1.f : 0.f;
            float g2 = g2p[b*8+e];
            a[2][e] += g2; a[3][e] += (g2 > 0.f) ? 1.f : 0.f;
        }
    }
    __shared__ float s[256][33];
#pragma unroll
    for (int t = 0; t < 4; t++)
#pragma unroll
        for (int e = 0; e < 8; e++) s[tid][t*8+e] = a[t][e];
    __syncthreads();
    for (int off = 128; off > 0; off >>= 1) {
        if (tid < off)
            for (int i = 0; i < 32; i++) s[tid][i] += s[tid+off][i];
        __syncthreads();
    }
    if (tid == 0) {
        float loss = 0.f;
        for (int t = 0; t < 4; t++) {
            float sum = 0.f;
            for (int e = 0; e < 8; e++) sum += s[0][t*8+e];
            float mean = sum / 8.f;
            float var = 0.f;
            for (int e = 0; e < 8; e++) { float d = s[0][t*8+e] - mean; var += d*d; }
            var /= 7.f;
            loss += var / (mean*mean + 1e-10f);
        }
        out[LOSS_OFF] = loss * 3e-5f;
    }
}

// ---------------- launch ----------------
extern "C" void kernel_launch(void* const* d_in, const int* in_sizes, int n_in,
                              void* d_out, int out_size) {
    const float* x    = (const float*)d_in[0];
    const float* c1w  = (const float*)d_in[1];
    const float* c1b  = (const float*)d_in[2];
    const float* c2w  = (const float*)d_in[3];
    const float* c2b  = (const float*)d_in[4];
    const float* wg1  = (const float*)d_in[5];
    const float* W1   = (const float*)d_in[6];
    const float* b1   = (const float*)d_in[7];
    const float* wg2  = (const float*)d_in[8];
    const float* W2   = (const float*)d_in[9];
    const float* b2   = (const float*)d_in[10];
    float* out = (float*)d_out;

    init_transpose_kernel<<<72, 256>>>(c2w);
    conv1_kernel<<<BATCH, 256>>>(x, c1w, c1b);
    conv2pool_kernel<<<dim3(4, BATCH), 192>>>(c2b, wg1);
    top2_kernel<<<16, 256>>>(out + G1_OFF);
    expert_gemm_kernel<<<dim3(64, NEXP, 2), 256>>>(W1, b1);
    moe2_kernel<<<512, 256>>>(wg2, W2, b2, out);
    loss_kernel<<<1, 256>>>(out);
}